// round 7
// baseline (speedup 1.0000x reference)
#include <cuda_runtime.h>

#define Hdim 1024
#define Wdim 1024
#define HWdim (Hdim * Wdim)
#define TS 32
#define NT 256

__device__ __forceinline__ float sigmoidf_(float y) {
    return 1.0f / (1.0f + __expf(-y));
}

__global__ __launch_bounds__(NT, 3) void unet_fused_kernel(
    const float* __restrict__ x,  const float* __restrict__ x2,
    const float* __restrict__ w1a, const float* __restrict__ b1a,
    const float* __restrict__ w2a, const float* __restrict__ b2a,
    const float* __restrict__ w3a, const float* __restrict__ b3a,
    const float* __restrict__ w1b, const float* __restrict__ b1b,
    const float* __restrict__ w2b, const float* __restrict__ b2b,
    const float* __restrict__ w3b, const float* __restrict__ b3b,
    const float* __restrict__ lw1, const float* __restrict__ lb1,
    const float* __restrict__ lw2, const float* __restrict__ lb2,
    float* __restrict__ outf, float* __restrict__ den1, float* __restrict__ den2)
{
    __shared__ float s_x[3 * 38 * 38];
    __shared__ float s_c4[36 * 36];
    __shared__ float s_c5[34 * 34];
    __shared__ float s_w[108];
    __shared__ float s_b[3];
    __shared__ float s_M[12];
    __shared__ float s_B2[2];

    const int tid = threadIdx.x;
    const int h0  = blockIdx.y * TS;
    const int w0  = blockIdx.x * TS;

    // ---- fold MLP (no inner nonlinearity): M = lw2@lw1, B = lw2@lb1+lb2 ----
    if (tid < 12) {
        int o = tid / 6, c = tid % 6;
        float acc = 0.0f;
        #pragma unroll 8
        for (int k = 0; k < 128; k++)
            acc += __ldg(&lw2[o * 128 + k]) * __ldg(&lw1[k * 6 + c]);
        s_M[tid] = acc;
    } else if (tid < 14) {
        int o = tid - 12;
        float acc = __ldg(&lb2[o]);
        #pragma unroll 8
        for (int k = 0; k < 128; k++)
            acc += __ldg(&lw2[o * 128 + k]) * __ldg(&lb1[k]);
        s_B2[o] = acc;
    }

    #pragma unroll 1
    for (int e = 0; e < 2; e++) {
        const float* X   = e ? x2  : x;
        const float* W1  = e ? w1b : w1a;
        const float* W2  = e ? w2b : w2a;
        const float* W3  = e ? w3b : w3a;
        const float* B1  = e ? b1b : b1a;
        const float* Bc2 = e ? b2b : b2a;
        const float* B3  = e ? b3b : b3a;
        float* den = e ? den2 : den1;

        __syncthreads();  // protect smem reuse across encoders

        // ---- load weights + biases ----
        if (tid < 108) {
            float v;
            if (tid < 27)      v = __ldg(&W1[tid]);
            else if (tid < 63) v = __ldg(&W2[tid - 27]);
            else               v = __ldg(&W3[tid - 63]);
            s_w[tid] = v;
        }
        if (tid == 120) s_b[0] = __ldg(&B1[0]);
        if (tid == 121) s_b[1] = __ldg(&Bc2[0]);
        if (tid == 122) s_b[2] = __ldg(&B3[0]);

        // ---- load input tile (3 ch, 3-halo, zero padded) ----
        #pragma unroll 1
        for (int c = 0; c < 3; c++) {
            #pragma unroll 1
            for (int idx = tid; idx < 38 * 38; idx += NT) {
                int r = idx / 38;
                int q = idx - r * 38;
                int gh = h0 - 3 + r, gw = w0 - 3 + q;
                float v = 0.0f;
                if ((unsigned)gh < (unsigned)Hdim && (unsigned)gw < (unsigned)Wdim)
                    v = __ldg(&X[c * HWdim + gh * Wdim + gw]);
                s_x[c * 1444 + idx] = v;
            }
        }
        __syncthreads();

        // ===== conv1: 3ch -> c4 (36x36), 2x2 blocked, float2 LDS =====
        // Outside-image positions must be 0 (reference zero-pads the
        // concatenated tensor).
        {
            float w[27];
            #pragma unroll
            for (int k = 0; k < 27; k++) w[k] = s_w[k];
            const float bia = s_b[0];

            #pragma unroll 1
            for (int item = tid; item < 18 * 18; item += NT) {
                int jp = item / 18;
                int ip = item - jp * 18;
                int j = jp * 2, i = ip * 2;
                float a00 = 0, a01 = 0, a10 = 0, a11 = 0;
                #pragma unroll
                for (int c = 0; c < 3; c++) {
                    const float* p = s_x + c * 1444 + j * 38 + i;
                    #pragma unroll
                    for (int rr = 0; rr < 4; rr++) {
                        float2 A = *(const float2*)(p + rr * 38);
                        float2 B = *(const float2*)(p + rr * 38 + 2);
                        if (rr <= 2) {
                            a00 += w[c*9+rr*3+0]*A.x + w[c*9+rr*3+1]*A.y + w[c*9+rr*3+2]*B.x;
                            a01 += w[c*9+rr*3+0]*A.y + w[c*9+rr*3+1]*B.x + w[c*9+rr*3+2]*B.y;
                        }
                        if (rr >= 1) {
                            a10 += w[c*9+(rr-1)*3+0]*A.x + w[c*9+(rr-1)*3+1]*A.y + w[c*9+(rr-1)*3+2]*B.x;
                            a11 += w[c*9+(rr-1)*3+0]*A.y + w[c*9+(rr-1)*3+1]*B.x + w[c*9+(rr-1)*3+2]*B.y;
                        }
                    }
                }
                int gw = w0 + i - 2, gh = h0 + j - 2;
                bool wc0 = (unsigned)gw < (unsigned)Wdim;
                bool wc1 = (unsigned)(gw + 1) < (unsigned)Wdim;
                bool hc0 = (unsigned)gh < (unsigned)Hdim;
                bool hc1 = (unsigned)(gh + 1) < (unsigned)Hdim;
                float2 r0 = make_float2(hc0 && wc0 ? sigmoidf_(bia + a00) : 0.0f,
                                        hc0 && wc1 ? sigmoidf_(bia + a01) : 0.0f);
                float2 r1 = make_float2(hc1 && wc0 ? sigmoidf_(bia + a10) : 0.0f,
                                        hc1 && wc1 ? sigmoidf_(bia + a11) : 0.0f);
                *(float2*)(s_c4 + j * 36 + i)       = r0;
                *(float2*)(s_c4 + (j + 1) * 36 + i) = r1;
            }
        }
        __syncthreads();

        // ===== conv2: [x,c4] -> c5 (34x34), 2x2 blocked, float2 LDS =====
        {
            float w[36];
            #pragma unroll
            for (int k = 0; k < 36; k++) w[k] = s_w[27 + k];
            const float bia = s_b[1];

            #pragma unroll 1
            for (int item = tid; item < 17 * 17; item += NT) {
                int jp = item / 17;
                int ip = item - jp * 17;
                int j = jp * 2, i = ip * 2;
                float a00 = 0, a01 = 0, a10 = 0, a11 = 0;
                // x channels: window rows j+1..j+4, cols i+1..i+4 (odd off: 3 loads)
                #pragma unroll
                for (int c = 0; c < 3; c++) {
                    const float* p = s_x + c * 1444 + (j + 1) * 38 + i;
                    #pragma unroll
                    for (int rr = 0; rr < 4; rr++) {
                        float2 A = *(const float2*)(p + rr * 38);
                        float2 B = *(const float2*)(p + rr * 38 + 2);
                        float2 C = *(const float2*)(p + rr * 38 + 4);
                        if (rr <= 2) {
                            a00 += w[c*9+rr*3+0]*A.y + w[c*9+rr*3+1]*B.x + w[c*9+rr*3+2]*B.y;
                            a01 += w[c*9+rr*3+0]*B.x + w[c*9+rr*3+1]*B.y + w[c*9+rr*3+2]*C.x;
                        }
                        if (rr >= 1) {
                            a10 += w[c*9+(rr-1)*3+0]*A.y + w[c*9+(rr-1)*3+1]*B.x + w[c*9+(rr-1)*3+2]*B.y;
                            a11 += w[c*9+(rr-1)*3+0]*B.x + w[c*9+(rr-1)*3+1]*B.y + w[c*9+(rr-1)*3+2]*C.x;
                        }
                    }
                }
                // c4 channel: rows j..j+3, cols i..i+3 (even: 2 loads)
                {
                    const float* p = s_c4 + j * 36 + i;
                    #pragma unroll
                    for (int rr = 0; rr < 4; rr++) {
                        float2 A = *(const float2*)(p + rr * 36);
                        float2 B = *(const float2*)(p + rr * 36 + 2);
                        if (rr <= 2) {
                            a00 += w[27+rr*3+0]*A.x + w[27+rr*3+1]*A.y + w[27+rr*3+2]*B.x;
                            a01 += w[27+rr*3+0]*A.y + w[27+rr*3+1]*B.x + w[27+rr*3+2]*B.y;
                        }
                        if (rr >= 1) {
                            a10 += w[27+(rr-1)*3+0]*A.x + w[27+(rr-1)*3+1]*A.y + w[27+(rr-1)*3+2]*B.x;
                            a11 += w[27+(rr-1)*3+0]*A.y + w[27+(rr-1)*3+1]*B.x + w[27+(rr-1)*3+2]*B.y;
                        }
                    }
                }
                int gw = w0 + i - 1, gh = h0 + j - 1;
                bool wc0 = (unsigned)gw < (unsigned)Wdim;
                bool wc1 = (unsigned)(gw + 1) < (unsigned)Wdim;
                bool hc0 = (unsigned)gh < (unsigned)Hdim;
                bool hc1 = (unsigned)(gh + 1) < (unsigned)Hdim;
                float2 r0 = make_float2(hc0 && wc0 ? sigmoidf_(bia + a00) : 0.0f,
                                        hc0 && wc1 ? sigmoidf_(bia + a01) : 0.0f);
                float2 r1 = make_float2(hc1 && wc0 ? sigmoidf_(bia + a10) : 0.0f,
                                        hc1 && wc1 ? sigmoidf_(bia + a11) : 0.0f);
                *(float2*)(s_c5 + j * 34 + i)       = r0;
                *(float2*)(s_c5 + (j + 1) * 34 + i) = r1;
            }
        }
        __syncthreads();

        // ===== conv3: [x,c4,c5] -> c6 + den + outf, 32x32, 1 item/thread =====
        {
            float w[45];
            #pragma unroll
            for (int k = 0; k < 45; k++) w[k] = s_w[63 + k];
            const float bia = s_b[2];

            const int jp = tid >> 4;
            const int ip = tid & 15;
            const int j = jp * 2, i = ip * 2;
            float a00 = 0, a01 = 0, a10 = 0, a11 = 0;

            // x channels: rows j+2..j+5, cols i+2..i+5 (even: 2 loads)
            #pragma unroll
            for (int c = 0; c < 3; c++) {
                const float* p = s_x + c * 1444 + (j + 2) * 38 + (i + 2);
                #pragma unroll
                for (int rr = 0; rr < 4; rr++) {
                    float2 A = *(const float2*)(p + rr * 38);
                    float2 B = *(const float2*)(p + rr * 38 + 2);
                    if (rr <= 2) {
                        a00 += w[c*9+rr*3+0]*A.x + w[c*9+rr*3+1]*A.y + w[c*9+rr*3+2]*B.x;
                        a01 += w[c*9+rr*3+0]*A.y + w[c*9+rr*3+1]*B.x + w[c*9+rr*3+2]*B.y;
                    }
                    if (rr >= 1) {
                        a10 += w[c*9+(rr-1)*3+0]*A.x + w[c*9+(rr-1)*3+1]*A.y + w[c*9+(rr-1)*3+2]*B.x;
                        a11 += w[c*9+(rr-1)*3+0]*A.y + w[c*9+(rr-1)*3+1]*B.x + w[c*9+(rr-1)*3+2]*B.y;
                    }
                }
            }
            // c4: rows j+1..j+4, cols i+1..i+4 (odd: 3 loads)
            {
                const float* p = s_c4 + (j + 1) * 36 + i;
                #pragma unroll
                for (int rr = 0; rr < 4; rr++) {
                    float2 A = *(const float2*)(p + rr * 36);
                    float2 B = *(const float2*)(p + rr * 36 + 2);
                    float2 C = *(const float2*)(p + rr * 36 + 4);
                    if (rr <= 2) {
                        a00 += w[27+rr*3+0]*A.y + w[27+rr*3+1]*B.x + w[27+rr*3+2]*B.y;
                        a01 += w[27+rr*3+0]*B.x + w[27+rr*3+1]*B.y + w[27+rr*3+2]*C.x;
                    }
                    if (rr >= 1) {
                        a10 += w[27+(rr-1)*3+0]*A.y + w[27+(rr-1)*3+1]*B.x + w[27+(rr-1)*3+2]*B.y;
                        a11 += w[27+(rr-1)*3+0]*B.x + w[27+(rr-1)*3+1]*B.y + w[27+(rr-1)*3+2]*C.x;
                    }
                }
            }
            // c5: rows j..j+3, cols i..i+3 (even: 2 loads)
            {
                const float* p = s_c5 + j * 34 + i;
                #pragma unroll
                for (int rr = 0; rr < 4; rr++) {
                    float2 A = *(const float2*)(p + rr * 34);
                    float2 B = *(const float2*)(p + rr * 34 + 2);
                    if (rr <= 2) {
                        a00 += w[36+rr*3+0]*A.x + w[36+rr*3+1]*A.y + w[36+rr*3+2]*B.x;
                        a01 += w[36+rr*3+0]*A.y + w[36+rr*3+1]*B.x + w[36+rr*3+2]*B.y;
                    }
                    if (rr >= 1) {
                        a10 += w[36+(rr-1)*3+0]*A.x + w[36+(rr-1)*3+1]*A.y + w[36+(rr-1)*3+2]*B.x;
                        a11 += w[36+(rr-1)*3+0]*A.y + w[36+(rr-1)*3+1]*B.x + w[36+(rr-1)*3+2]*B.y;
                    }
                }
            }

            float accs[2][2] = {{a00, a01}, {a10, a11}};
            #pragma unroll
            for (int r = 0; r < 2; r++) {
                #pragma unroll
                for (int cc = 0; cc < 2; cc++) {
                    int jj = j + r, ii = i + cc;
                    float f5 = sigmoidf_(bia + accs[r][cc]);
                    float f0 = s_x[0 * 1444 + (jj + 3) * 38 + (ii + 3)];
                    float f1 = s_x[1 * 1444 + (jj + 3) * 38 + (ii + 3)];
                    float f2 = s_x[2 * 1444 + (jj + 3) * 38 + (ii + 3)];
                    float f3 = s_c4[(jj + 2) * 36 + (ii + 2)];
                    float f4 = s_c5[(jj + 1) * 34 + (ii + 1)];

                    int pix = (h0 + jj) * Wdim + (w0 + ii);
                    float2* dp = (float2*)(den + (size_t)pix * 6);
                    dp[0] = make_float2(f0, f1);
                    dp[1] = make_float2(f2, f3);
                    dp[2] = make_float2(f4, f5);

                    float m0 = s_M[0]*f0 + s_M[1]*f1 + s_M[2]*f2
                             + s_M[3]*f3 + s_M[4]*f4 + s_M[5]*f5;
                    float m1 = s_M[6]*f0 + s_M[7]*f1 + s_M[8]*f2
                             + s_M[9]*f3 + s_M[10]*f4 + s_M[11]*f5;
                    float2* op = (float2*)outf + pix;
                    if (e == 0) {
                        *op = make_float2(s_B2[0] + m0, s_B2[1] + m1);
                    } else {
                        float2 prev = *op;  // same thread wrote it in e=0
                        *op = make_float2(prev.x - m0, prev.y - m1);
                    }
                }
            }
        }
    }
}

extern "C" void kernel_launch(void* const* d_in, const int* in_sizes, int n_in,
                              void* d_out, int out_size) {
    const float* x   = (const float*)d_in[0];
    const float* x2  = (const float*)d_in[1];
    const float* w1a = (const float*)d_in[2];
    const float* b1a = (const float*)d_in[3];
    const float* w2a = (const float*)d_in[4];
    const float* b2a = (const float*)d_in[5];
    const float* w3a = (const float*)d_in[6];
    const float* b3a = (const float*)d_in[7];
    const float* w1b = (const float*)d_in[8];
    const float* b1b = (const float*)d_in[9];
    const float* w2b = (const float*)d_in[10];
    const float* b2b = (const float*)d_in[11];
    const float* w3b = (const float*)d_in[12];
    const float* b3b = (const float*)d_in[13];
    const float* lw1 = (const float*)d_in[14];
    const float* lb1 = (const float*)d_in[15];
    const float* lw2 = (const float*)d_in[16];
    const float* lb2 = (const float*)d_in[17];

    float* outf = (float*)d_out;                       // [HW, 2]
    float* den1 = (float*)d_out + (size_t)2 * HWdim;   // [H, W, 6]
    float* den2 = (float*)d_out + (size_t)8 * HWdim;   // [H, W, 6]

    dim3 grid(Wdim / TS, Hdim / TS);
    unet_fused_kernel<<<grid, NT>>>(
        x, x2, w1a, b1a, w2a, b2a, w3a, b3a,
        w1b, b1b, w2b, b2b, w3b, b3b,
        lw1, lb1, lw2, lb2,
        outf, den1, den2);
}

// round 8
// speedup vs baseline: 1.2420x; 1.2420x over previous
#include <cuda_runtime.h>

#define Hdim 1024
#define Wdim 1024
#define HWdim (Hdim * Wdim)
#define TSH 64
#define TSW 32
#define NT 256

// smem float offsets
#define OFF_X   0            // [3][70][38]
#define OFF_C4  7980         // [68][36]
#define OFF_C5  10428        // [66][34]
#define OFF_W   12672        // [108]
#define OFF_B   12780        // [3]
#define OFF_M   12783        // [12]
#define OFF_B2  12795        // [2]
#define SMEM_FLOATS 12797
#define SMEM_BYTES (SMEM_FLOATS * 4)

__device__ float g_M[12];
__device__ float g_B[2];

__global__ void fold_mlp_kernel(const float* __restrict__ lw1,
                                const float* __restrict__ lb1,
                                const float* __restrict__ lw2,
                                const float* __restrict__ lb2) {
    int t = threadIdx.x;
    if (t < 12) {
        int o = t / 6, c = t % 6;
        float acc = 0.0f;
        #pragma unroll 8
        for (int k = 0; k < 128; k++)
            acc += lw2[o * 128 + k] * lw1[k * 6 + c];
        g_M[t] = acc;
    } else if (t < 14) {
        int o = t - 12;
        float acc = lb2[o];
        #pragma unroll 8
        for (int k = 0; k < 128; k++)
            acc += lw2[o * 128 + k] * lb1[k];
        g_B[o] = acc;
    }
}

__device__ __forceinline__ float sigmoidf_(float y) {
    return 1.0f / (1.0f + __expf(-y));
}

__global__ __launch_bounds__(NT, 3) void unet_fused_kernel(
    const float* __restrict__ x,  const float* __restrict__ x2,
    const float* __restrict__ w1a, const float* __restrict__ b1a,
    const float* __restrict__ w2a, const float* __restrict__ b2a,
    const float* __restrict__ w3a, const float* __restrict__ b3a,
    const float* __restrict__ w1b, const float* __restrict__ b1b,
    const float* __restrict__ w2b, const float* __restrict__ b2b,
    const float* __restrict__ w3b, const float* __restrict__ b3b,
    float* __restrict__ outf, float* __restrict__ den1, float* __restrict__ den2)
{
    extern __shared__ float sm[];
    float* s_x  = sm + OFF_X;    // [3][70][38], row stride 38, ch stride 2660
    float* s_c4 = sm + OFF_C4;   // [68][36]
    float* s_c5 = sm + OFF_C5;   // [66][34]
    float* s_w  = sm + OFF_W;
    float* s_b  = sm + OFF_B;
    float* s_M  = sm + OFF_M;
    float* s_B2 = sm + OFF_B2;

    const int tid = threadIdx.x;
    const int h0  = blockIdx.y * TSH;
    const int w0  = blockIdx.x * TSW;

    if (tid < 12) s_M[tid] = g_M[tid];
    if (tid >= 12 && tid < 14) s_B2[tid - 12] = g_B[tid - 12];

    #pragma unroll 1
    for (int e = 0; e < 2; e++) {
        const float* X   = e ? x2  : x;
        const float* W1  = e ? w1b : w1a;
        const float* W2  = e ? w2b : w2a;
        const float* W3  = e ? w3b : w3a;
        const float* B1  = e ? b1b : b1a;
        const float* Bc2 = e ? b2b : b2a;
        const float* B3  = e ? b3b : b3a;
        float* den = e ? den2 : den1;

        __syncthreads();  // protect smem reuse across encoders

        // ---- weights + biases ----
        if (tid < 108) {
            float v;
            if (tid < 27)      v = __ldg(&W1[tid]);
            else if (tid < 63) v = __ldg(&W2[tid - 27]);
            else               v = __ldg(&W3[tid - 63]);
            s_w[tid] = v;
        }
        if (tid == 120) s_b[0] = __ldg(&B1[0]);
        if (tid == 121) s_b[1] = __ldg(&Bc2[0]);
        if (tid == 122) s_b[2] = __ldg(&B3[0]);

        // ---- input tile (3 ch, 70x38, 3-halo, zero padded) ----
        #pragma unroll 1
        for (int c = 0; c < 3; c++) {
            #pragma unroll 1
            for (int idx = tid; idx < 70 * 38; idx += NT) {
                int r = idx / 38;
                int q = idx - r * 38;
                int gh = h0 - 3 + r, gw = w0 - 3 + q;
                float v = 0.0f;
                if ((unsigned)gh < (unsigned)Hdim && (unsigned)gw < (unsigned)Wdim)
                    v = __ldg(&X[c * HWdim + gh * Wdim + gw]);
                s_x[c * 2660 + idx] = v;
            }
        }
        __syncthreads();

        // ===== conv1: 3ch -> c4 (68x36), 2-row blocked =====
        // Outside-image positions must be 0 (reference zero-pads the
        // concatenated tensor).
        {
            float w[27];
            #pragma unroll
            for (int k = 0; k < 27; k++) w[k] = s_w[k];
            const float bia = s_b[0];

            #pragma unroll 1
            for (int item = tid; item < 34 * 36; item += NT) {
                int jp = item / 36;
                int i  = item - jp * 36;
                int j  = jp * 2;
                float a0 = 0, a1 = 0, a2 = 0;
                float c0 = 0, c1 = 0, c2 = 0;
                #pragma unroll
                for (int c = 0; c < 3; c++) {
                    const float* p = s_x + c * 2660 + j * 38 + i;
                    float r00 = p[0],   r01 = p[1],   r02 = p[2];
                    float r10 = p[38],  r11 = p[39],  r12 = p[40];
                    float r20 = p[76],  r21 = p[77],  r22 = p[78];
                    float r30 = p[114], r31 = p[115], r32 = p[116];
                    float ta = w[c*9+0]*r00 + w[c*9+1]*r01 + w[c*9+2]*r02
                             + w[c*9+3]*r10 + w[c*9+4]*r11 + w[c*9+5]*r12
                             + w[c*9+6]*r20 + w[c*9+7]*r21 + w[c*9+8]*r22;
                    float tb = w[c*9+0]*r10 + w[c*9+1]*r11 + w[c*9+2]*r12
                             + w[c*9+3]*r20 + w[c*9+4]*r21 + w[c*9+5]*r22
                             + w[c*9+6]*r30 + w[c*9+7]*r31 + w[c*9+8]*r32;
                    if (c == 0) { a0 = ta; c0 = tb; }
                    else if (c == 1) { a1 = ta; c1 = tb; }
                    else { a2 = ta; c2 = tb; }
                }
                int gw = w0 + i - 2;
                bool wi = (unsigned)gw < (unsigned)Wdim;
                int gh = h0 + j - 2;
                bool i0 = wi && (unsigned)gh < (unsigned)Hdim;
                bool i1 = wi && (unsigned)(gh + 1) < (unsigned)Hdim;
                s_c4[j * 36 + i]       = i0 ? sigmoidf_(bia + (a0 + a1) + a2) : 0.0f;
                s_c4[(j + 1) * 36 + i] = i1 ? sigmoidf_(bia + (c0 + c1) + c2) : 0.0f;
            }
        }
        __syncthreads();

        // ===== conv2: [x,c4] -> c5 (66x34), 2-row blocked =====
        {
            float w[36];
            #pragma unroll
            for (int k = 0; k < 36; k++) w[k] = s_w[27 + k];
            const float bia = s_b[1];

            #pragma unroll 1
            for (int item = tid; item < 33 * 34; item += NT) {
                int jp = item / 34;
                int i  = item - jp * 34;
                int j  = jp * 2;
                float a0 = 0, a1 = 0, a2 = 0, a3 = 0;
                float c0 = 0, c1 = 0, c2 = 0, c3 = 0;
                #pragma unroll
                for (int c = 0; c < 3; c++) {
                    const float* p = s_x + c * 2660 + (j + 1) * 38 + (i + 1);
                    float r00 = p[0],   r01 = p[1],   r02 = p[2];
                    float r10 = p[38],  r11 = p[39],  r12 = p[40];
                    float r20 = p[76],  r21 = p[77],  r22 = p[78];
                    float r30 = p[114], r31 = p[115], r32 = p[116];
                    float ta = w[c*9+0]*r00 + w[c*9+1]*r01 + w[c*9+2]*r02
                             + w[c*9+3]*r10 + w[c*9+4]*r11 + w[c*9+5]*r12
                             + w[c*9+6]*r20 + w[c*9+7]*r21 + w[c*9+8]*r22;
                    float tb = w[c*9+0]*r10 + w[c*9+1]*r11 + w[c*9+2]*r12
                             + w[c*9+3]*r20 + w[c*9+4]*r21 + w[c*9+5]*r22
                             + w[c*9+6]*r30 + w[c*9+7]*r31 + w[c*9+8]*r32;
                    if (c == 0) { a0 = ta; c0 = tb; }
                    else if (c == 1) { a1 = ta; c1 = tb; }
                    else { a2 = ta; c2 = tb; }
                }
                {
                    const float* p = s_c4 + j * 36 + i;
                    float r00 = p[0],   r01 = p[1],   r02 = p[2];
                    float r10 = p[36],  r11 = p[37],  r12 = p[38];
                    float r20 = p[72],  r21 = p[73],  r22 = p[74];
                    float r30 = p[108], r31 = p[109], r32 = p[110];
                    a3 = w[27]*r00 + w[28]*r01 + w[29]*r02
                       + w[30]*r10 + w[31]*r11 + w[32]*r12
                       + w[33]*r20 + w[34]*r21 + w[35]*r22;
                    c3 = w[27]*r10 + w[28]*r11 + w[29]*r12
                       + w[30]*r20 + w[31]*r21 + w[32]*r22
                       + w[33]*r30 + w[34]*r31 + w[35]*r32;
                }
                int gw = w0 + i - 1;
                bool wi = (unsigned)gw < (unsigned)Wdim;
                int gh = h0 + j - 1;
                bool i0 = wi && (unsigned)gh < (unsigned)Hdim;
                bool i1 = wi && (unsigned)(gh + 1) < (unsigned)Hdim;
                s_c5[j * 34 + i]       = i0 ? sigmoidf_(bia + (a0 + a1) + (a2 + a3)) : 0.0f;
                s_c5[(j + 1) * 34 + i] = i1 ? sigmoidf_(bia + (c0 + c1) + (c2 + c3)) : 0.0f;
            }
        }
        __syncthreads();

        // ===== conv3: [x,c4,c5] -> c6 + den + outf (64x32), 4 items/thread =====
        {
            float w[45];
            #pragma unroll
            for (int k = 0; k < 45; k++) w[k] = s_w[63 + k];
            const float bia = s_b[2];

            #pragma unroll 1
            for (int k = 0; k < 4; k++) {
                int item = tid + k * NT;     // 1024 items exactly
                int jp = item >> 5;
                int i  = item & 31;
                int j  = jp * 2;
                float a0 = 0, a1 = 0, a2 = 0, a3 = 0, a4 = 0;
                float c0 = 0, c1 = 0, c2 = 0, c3 = 0, c4v = 0;
                #pragma unroll
                for (int c = 0; c < 3; c++) {
                    const float* p = s_x + c * 2660 + (j + 2) * 38 + (i + 2);
                    float r00 = p[0],   r01 = p[1],   r02 = p[2];
                    float r10 = p[38],  r11 = p[39],  r12 = p[40];
                    float r20 = p[76],  r21 = p[77],  r22 = p[78];
                    float r30 = p[114], r31 = p[115], r32 = p[116];
                    float ta = w[c*9+0]*r00 + w[c*9+1]*r01 + w[c*9+2]*r02
                             + w[c*9+3]*r10 + w[c*9+4]*r11 + w[c*9+5]*r12
                             + w[c*9+6]*r20 + w[c*9+7]*r21 + w[c*9+8]*r22;
                    float tb = w[c*9+0]*r10 + w[c*9+1]*r11 + w[c*9+2]*r12
                             + w[c*9+3]*r20 + w[c*9+4]*r21 + w[c*9+5]*r22
                             + w[c*9+6]*r30 + w[c*9+7]*r31 + w[c*9+8]*r32;
                    if (c == 0) { a0 = ta; c0 = tb; }
                    else if (c == 1) { a1 = ta; c1 = tb; }
                    else { a2 = ta; c2 = tb; }
                }
                {
                    const float* p = s_c4 + (j + 1) * 36 + (i + 1);
                    float r00 = p[0],   r01 = p[1],   r02 = p[2];
                    float r10 = p[36],  r11 = p[37],  r12 = p[38];
                    float r20 = p[72],  r21 = p[73],  r22 = p[74];
                    float r30 = p[108], r31 = p[109], r32 = p[110];
                    a3 = w[27]*r00 + w[28]*r01 + w[29]*r02
                       + w[30]*r10 + w[31]*r11 + w[32]*r12
                       + w[33]*r20 + w[34]*r21 + w[35]*r22;
                    c3 = w[27]*r10 + w[28]*r11 + w[29]*r12
                       + w[30]*r20 + w[31]*r21 + w[32]*r22
                       + w[33]*r30 + w[34]*r31 + w[35]*r32;
                }
                {
                    const float* p = s_c5 + j * 34 + i;
                    float r00 = p[0],   r01 = p[1],   r02 = p[2];
                    float r10 = p[34],  r11 = p[35],  r12 = p[36];
                    float r20 = p[68],  r21 = p[69],  r22 = p[70];
                    float r30 = p[102], r31 = p[103], r32 = p[104];
                    a4 = w[36]*r00 + w[37]*r01 + w[38]*r02
                       + w[39]*r10 + w[40]*r11 + w[41]*r12
                       + w[42]*r20 + w[43]*r21 + w[44]*r22;
                    c4v = w[36]*r10 + w[37]*r11 + w[38]*r12
                        + w[39]*r20 + w[40]*r21 + w[41]*r22
                        + w[42]*r30 + w[43]*r31 + w[44]*r32;
                }

                #pragma unroll
                for (int r = 0; r < 2; r++) {
                    int jj = j + r;
                    float f5 = sigmoidf_(bia + (r == 0
                                 ? ((a0 + a1) + (a2 + a3) + a4)
                                 : ((c0 + c1) + (c2 + c3) + c4v)));
                    float f0 = s_x[0 * 2660 + (jj + 3) * 38 + (i + 3)];
                    float f1 = s_x[1 * 2660 + (jj + 3) * 38 + (i + 3)];
                    float f2 = s_x[2 * 2660 + (jj + 3) * 38 + (i + 3)];
                    float f3 = s_c4[(jj + 2) * 36 + (i + 2)];
                    float f4 = s_c5[(jj + 1) * 34 + (i + 1)];

                    int pix = (h0 + jj) * Wdim + (w0 + i);
                    float2* dp = (float2*)(den + (size_t)pix * 6);
                    dp[0] = make_float2(f0, f1);
                    dp[1] = make_float2(f2, f3);
                    dp[2] = make_float2(f4, f5);

                    float m0 = s_M[0]*f0 + s_M[1]*f1 + s_M[2]*f2
                             + s_M[3]*f3 + s_M[4]*f4 + s_M[5]*f5;
                    float m1 = s_M[6]*f0 + s_M[7]*f1 + s_M[8]*f2
                             + s_M[9]*f3 + s_M[10]*f4 + s_M[11]*f5;
                    float2* op = (float2*)outf + pix;
                    if (e == 0) {
                        *op = make_float2(s_B2[0] + m0, s_B2[1] + m1);
                    } else {
                        float2 prev = *op;  // same thread wrote it in e=0
                        *op = make_float2(prev.x - m0, prev.y - m1);
                    }
                }
            }
        }
    }
}

extern "C" void kernel_launch(void* const* d_in, const int* in_sizes, int n_in,
                              void* d_out, int out_size) {
    const float* x   = (const float*)d_in[0];
    const float* x2  = (const float*)d_in[1];
    const float* w1a = (const float*)d_in[2];
    const float* b1a = (const float*)d_in[3];
    const float* w2a = (const float*)d_in[4];
    const float* b2a = (const float*)d_in[5];
    const float* w3a = (const float*)d_in[6];
    const float* b3a = (const float*)d_in[7];
    const float* w1b = (const float*)d_in[8];
    const float* b1b = (const float*)d_in[9];
    const float* w2b = (const float*)d_in[10];
    const float* b2b = (const float*)d_in[11];
    const float* w3b = (const float*)d_in[12];
    const float* b3b = (const float*)d_in[13];
    const float* lw1 = (const float*)d_in[14];
    const float* lb1 = (const float*)d_in[15];
    const float* lw2 = (const float*)d_in[16];
    const float* lb2 = (const float*)d_in[17];

    float* outf = (float*)d_out;                       // [HW, 2]
    float* den1 = (float*)d_out + (size_t)2 * HWdim;   // [H, W, 6]
    float* den2 = (float*)d_out + (size_t)8 * HWdim;   // [H, W, 6]

    cudaFuncSetAttribute(unet_fused_kernel,
                         cudaFuncAttributeMaxDynamicSharedMemorySize, SMEM_BYTES);

    fold_mlp_kernel<<<1, 32>>>(lw1, lb1, lw2, lb2);

    dim3 grid(Wdim / TSW, Hdim / TSH);
    unet_fused_kernel<<<grid, NT, SMEM_BYTES>>>(
        x, x2, w1a, b1a, w2a, b2a, w3a, b3a,
        w1b, b1b, w2b, b2b, w3b, b3b,
        outf, den1, den2);
}